// round 14
// baseline (speedup 1.0000x reference)
#include <cuda_runtime.h>
#include <cuda_fp16.h>
#include <cstdint>

#define B_ 16
#define L_ 2048
#define D_ 64
#define NE (B_*L_*D_)
#define CE 0.18033688011112042f     // (1/8)*log2(e)
#define BCH 4                       // batches per chunk
#define NCH (B_/BCH)                // 4 chunks

// device scratch (no allocation)
__device__ __half g_Qf[NE], g_Kf[NE];                 // fp16 Q, K [b][row][d]
__device__ __half g_VT[NE];                           // fp16 V transposed [b][d][k]
__device__ __half g_u[(size_t)B_*L_*L_];              // u, tile-blocked swizzled 8KB tiles
__device__ float2 g_Psum[2*B_*L_];                    // per-z partial (sum_all, sum_unmasked)
__device__ float g_I[B_*L_];                          // per-row 1/denom

// ---------------------------------------------------------------- helpers
__device__ __forceinline__ uint32_t smem_u32(const void* p) {
    return (uint32_t)__cvta_generic_to_shared(p);
}
__device__ __forceinline__ void cp16(uint32_t dst, const void* src) {
    asm volatile("cp.async.cg.shared.global [%0], [%1], 16;" :: "r"(dst), "l"(src));
}
__device__ __forceinline__ void cp_commit() { asm volatile("cp.async.commit_group;"); }
__device__ __forceinline__ void cp_wait0()  { asm volatile("cp.async.wait_group 0;"); }

__device__ __forceinline__ void ldsm_x4(uint32_t& r0, uint32_t& r1, uint32_t& r2, uint32_t& r3,
                                        uint32_t addr) {
    asm volatile("ldmatrix.sync.aligned.m8n8.x4.shared.b16 {%0,%1,%2,%3}, [%4];"
                 : "=r"(r0), "=r"(r1), "=r"(r2), "=r"(r3) : "r"(addr));
}
__device__ __forceinline__ void mma_f16(float* c,
                                        uint32_t a0, uint32_t a1, uint32_t a2, uint32_t a3,
                                        uint32_t b0, uint32_t b1) {
    asm volatile(
        "mma.sync.aligned.m16n8k16.row.col.f32.f16.f16.f32 "
        "{%0,%1,%2,%3}, {%4,%5,%6,%7}, {%8,%9}, {%0,%1,%2,%3};\n"
        : "+f"(c[0]), "+f"(c[1]), "+f"(c[2]), "+f"(c[3])
        : "r"(a0), "r"(a1), "r"(a2), "r"(a3), "r"(b0), "r"(b1));
}

// ---------------------------------------------------------------- K0a: Q/K -> fp16
__global__ __launch_bounds__(256) void prep_qk(const float* __restrict__ q,
                                               const float* __restrict__ k, int n) {
    int i = (blockIdx.x * blockDim.x + threadIdx.x) * 2;
    const float* src = blockIdx.y ? k : q;
    __half* dst = blockIdx.y ? g_Kf : g_Qf;
    if (i < n) {
        float2 x = *(const float2*)(src + i);
        *(__half2*)(dst + i) = __floats2half2_rn(x.x, x.y);
    }
}

// ---------------------------------------------------------------- K0b: V transpose -> [b][d][k] fp16
__global__ __launch_bounds__(256) void vtrans_kernel(const float* __restrict__ v) {
    __shared__ float t[32][33];
    int b = blockIdx.z, d0 = blockIdx.y * 32, k0 = blockIdx.x * 32;
    int tx = threadIdx.x, ty = threadIdx.y;   // block (32,8)
    #pragma unroll
    for (int j = 0; j < 32; j += 8)
        t[ty + j][tx] = v[((size_t)b * L_ + k0 + ty + j) * D_ + d0 + tx];
    __syncthreads();
    #pragma unroll
    for (int j = 0; j < 32; j += 8) {
        int d = d0 + ty + j;
        g_VT[((size_t)b * D_ + d) * L_ + k0 + tx] = __float2half_rn(t[tx][ty + j]);
    }
}

// ---------------- K1: fp16 scores GEMM + exp + mask + partial row sums (split-K z=2)
// grid (L/64, BCH, 2), block 128 (4 warps x 16 rows). Dyn smem 32768B.
__global__ __launch_bounds__(128, 5) void scores_kernel(const int* __restrict__ mask, int b0) {
    extern __shared__ char smem[];
    const int QF = 0, KB0 = 8192, US = 24576;
    int b = b0 + blockIdx.y, m0 = blockIdx.x * 64, z = blockIdx.z, tid = threadIdx.x;
    int warp = tid >> 5, lane = tid & 31, gid = lane >> 2, tig = lane & 3;
    uint32_t sm = smem_u32(smem);
    int kt0 = z * 16;

    // prologue: Q + K(kt0)
    {
        const __half* qsrc = g_Qf + ((size_t)b * L_ + m0) * D_;
        const __half* ksrc = g_Kf + ((size_t)b * L_ + kt0 * 64) * D_;
        #pragma unroll
        for (int it = 0; it < 4; it++) {
            int i = tid + it * 128, r = i >> 3, c = i & 7;
            uint32_t o = r * 128 + ((c ^ (r & 7)) * 16);
            cp16(sm + QF + o, qsrc + r * 64 + c * 8);
            cp16(sm + KB0 + o, ksrc + r * 64 + c * 8);
        }
        cp_commit();
    }

    uint32_t sw = lane & 7;
    uint32_t cA = lane >> 4;            // 0/1
    uint32_t cB = (lane >> 3) & 1;      // 0/1
    int rA = warp * 16 + (lane & 15);
    uint32_t aQ = sm + QF + rA * 128;
    uint32_t rowBoff[4];
    #pragma unroll
    for (int g = 0; g < 4; g++)
        rowBoff[g] = (uint32_t)((g * 16 + ((lane >> 4) & 1) * 8 + (lane & 7)) * 128);

    int r0 = warp * 16 + gid, r1 = r0 + 8;
    const int* mrow0 = mask + ((size_t)(b * L_ + m0 + r0)) * L_ + tig * 2;
    const int* mrow1 = mask + ((size_t)(b * L_ + m0 + r1)) * L_ + tig * 2;

    // u staging addresses (swizzled within the 8KB tile)
    char* usr0 = smem + US + r0 * 128 + tig * 4;
    char* usr1 = smem + US + r1 * 128 + tig * 4;
    int swr0 = r0 & 7, swr1 = r1 & 7;
    uint4* gUrow = (uint4*)(g_u + (((size_t)b * 32 + (m0 >> 6)) * 32) * 4096);

    float rsa0 = 0.f, rsa1 = 0.f, rsu0 = 0.f, rsu1 = 0.f;

    for (int t = 0; t < 16; t++) {
        int kt = kt0 + t;
        int d = t & 1, n0 = kt * 64;
        cp_wait0();
        __syncthreads();

        // mask prefetch into registers (latency covered by scores GEMM)
        int2 mk0[8], mk1[8];
        #pragma unroll
        for (int j = 0; j < 8; j++) {
            mk0[j] = __ldg((const int2*)(mrow0 + n0 + j*8));
            mk1[j] = __ldg((const int2*)(mrow1 + n0 + j*8));
        }

        if (t < 15) {               // prefetch K(kt+1)
            int d2 = (t + 1) & 1, n2 = (kt + 1) * 64;
            const __half* ksrc = g_Kf + ((size_t)b * L_ + n2) * D_;
            #pragma unroll
            for (int it = 0; it < 4; it++) {
                int i = tid + it * 128, r = i >> 3, c = i & 7;
                uint32_t o = r * 128 + ((c ^ (r & 7)) * 16);
                cp16(sm + KB0 + d2 * 8192 + o, ksrc + r * 64 + c * 8);
            }
            cp_commit();
        }

        // ---- scores: S(16x64) = Q_warp(16x64) · K^T(64x64), single fp16 GEMM
        float accS[8][4];
        #pragma unroll
        for (int j = 0; j < 8; j++)
            #pragma unroll
            for (int x = 0; x < 4; x++) accS[j][x] = 0.f;

        uint32_t kb_base = sm + KB0 + d * 8192;
        #pragma unroll
        for (int kk = 0; kk < 4; kk++) {
            uint32_t oA = ((cA + 2*kk) ^ sw) * 16;
            uint32_t oB = ((cB + 2*kk) ^ sw) * 16;
            uint32_t a[4];
            ldsm_x4(a[0], a[1], a[2], a[3], aQ + oA);
            #pragma unroll
            for (int g = 0; g < 4; g++) {
                uint32_t bfr[4];
                ldsm_x4(bfr[0], bfr[1], bfr[2], bfr[3], kb_base + rowBoff[g] + oB);
                mma_f16(accS[g*2],   a[0], a[1], a[2], a[3], bfr[0], bfr[1]);
                mma_f16(accS[g*2+1], a[0], a[1], a[2], a[3], bfr[2], bfr[3]);
            }
        }

        // ---- epilogue: exp, mask, sums, STS u into swizzled staging tile
        #pragma unroll
        for (int j = 0; j < 8; j++) {
            float e0 = exp2f(accS[j][0] * CE);
            float e1 = exp2f(accS[j][1] * CE);
            float e2 = exp2f(accS[j][2] * CE);
            float e3 = exp2f(accS[j][3] * CE);
            rsa0 += e0 + e1;
            rsa1 += e2 + e3;
            float a0 = mk0[j].x ? 0.f : e0;
            float a1 = mk0[j].y ? 0.f : e1;
            float a2 = mk1[j].x ? 0.f : e2;
            float a3 = mk1[j].y ? 0.f : e3;
            rsu0 += a0 + a1;
            rsu1 += a2 + a3;
            *(__half2*)(usr0 + ((j ^ swr0) * 16)) = __floats2half2_rn(a0, a1);
            *(__half2*)(usr1 + ((j ^ swr1) * 16)) = __floats2half2_rn(a2, a3);
        }
        __syncthreads();   // staging tile complete

        // ---- coalesced STG.128 of the 8KB swizzled tile
        {
            uint4* gU = gUrow + (size_t)kt * 512;
            const uint4* sU = (const uint4*)(smem + US);
            #pragma unroll
            for (int it = 0; it < 4; it++)
                gU[tid + it * 128] = sU[tid + it * 128];
        }
    }

    // ---- partial sums: butterfly over tig lanes, write per-z
    #pragma unroll
    for (int o = 1; o <= 2; o <<= 1) {
        rsa0 += __shfl_xor_sync(0xffffffffu, rsa0, o);
        rsa1 += __shfl_xor_sync(0xffffffffu, rsa1, o);
        rsu0 += __shfl_xor_sync(0xffffffffu, rsu0, o);
        rsu1 += __shfl_xor_sync(0xffffffffu, rsu1, o);
    }
    if (tig == 0) {
        g_Psum[z * (B_*L_) + b * L_ + m0 + r0] = make_float2(rsa0, rsu0);
        g_Psum[z * (B_*L_) + b * L_ + m0 + r1] = make_float2(rsa1, rsu1);
    }
}

// ---------------------------------------------------------------- K1b: combine partials -> g_I
__global__ __launch_bounds__(256) void combine_kernel(int b0) {
    int row = b0 * L_ + blockIdx.x * blockDim.x + threadIdx.x;
    float2 p0 = g_Psum[row];
    float2 p1 = g_Psum[B_*L_ + row];
    g_I[row] = 1.f / ((p0.y + p1.y) + 1e-8f * (p0.x + p1.x));
}

// ---------------- K2: read tile-blocked u -> attn=u*I write + O += u@V*I (split-K z=2)
// grid (L/64, BCH, 2), block 128. Dyn smem 33024B. atomicAdd into zeroed out.
__global__ __launch_bounds__(128, 6) void av_kernel(float* __restrict__ attn,
                                                    float* __restrict__ out, int b0) {
    extern __shared__ char smem[];
    const int UB = 0, VB = 16384, SI = 32768;
    int b = b0 + blockIdx.y, m0 = blockIdx.x * 64, z = blockIdx.z, tid = threadIdx.x;
    int warp = tid >> 5, lane = tid & 31, gid = lane >> 2, tig = lane & 3;
    uint32_t sm = smem_u32(smem);
    float* sI = (float*)(smem + SI);
    int kt0 = z * 16;

    if (tid < 64) sI[tid] = g_I[b * L_ + m0 + tid];

    const uint4* gUrow = (const uint4*)(g_u + (((size_t)b * 32 + (m0 >> 6)) * 32) * 4096);

    // prologue: U(kt0) linear copy, V(kt0)
    {
        const uint4* ub = gUrow + (size_t)kt0 * 512;
        #pragma unroll
        for (int it = 0; it < 4; it++)
            cp16(sm + UB + (tid + it * 128) * 16, ub + tid + it * 128);
        #pragma unroll
        for (int it = 0; it < 4; it++) {
            int i = tid + it * 128, r = i >> 3, c = i & 7;
            uint32_t o = r * 128 + ((c ^ (r & 7)) * 16);
            cp16(sm + VB + o, g_VT + ((size_t)b * D_ + r) * L_ + kt0 * 64 + c * 8);
        }
        cp_commit();
    }

    uint32_t sw = lane & 7;
    uint32_t cA = lane >> 4;
    uint32_t cB = (lane >> 3) & 1;
    int rA = warp * 16 + (lane & 15);
    uint32_t rowBoff[4];
    #pragma unroll
    for (int g = 0; g < 4; g++)
        rowBoff[g] = (uint32_t)((g * 16 + ((lane >> 4) & 1) * 8 + (lane & 7)) * 128);

    int r0 = warp * 16 + gid, r1 = r0 + 8;

    float accO[8][4];
    #pragma unroll
    for (int j = 0; j < 8; j++)
        #pragma unroll
        for (int x = 0; x < 4; x++) accO[j][x] = 0.f;

    float I0 = 0.f, I1 = 0.f;

    for (int t = 0; t < 16; t++) {
        int kt = kt0 + t;
        int d = t & 1, n0 = kt * 64;
        cp_wait0();
        __syncthreads();
        if (t == 0) { I0 = sI[r0]; I1 = sI[r1]; }

        if (t < 15) {               // prefetch U,V(kt+1)
            int d2 = (t + 1) & 1, n2 = (kt + 1) * 64;
            const uint4* ub = gUrow + (size_t)(kt + 1) * 512;
            #pragma unroll
            for (int it = 0; it < 4; it++)
                cp16(sm + UB + d2 * 8192 + (tid + it * 128) * 16, ub + tid + it * 128);
            #pragma unroll
            for (int it = 0; it < 4; it++) {
                int i = tid + it * 128, r = i >> 3, c = i & 7;
                uint32_t o = r * 128 + ((c ^ (r & 7)) * 16);
                cp16(sm + VB + d2 * 8192 + o, g_VT + ((size_t)b * D_ + r) * L_ + n2 + c * 8);
            }
            cp_commit();
        }

        uint32_t aU = sm + UB + d * 8192 + rA * 128;
        uint32_t vb_base = sm + VB + d * 8192;

        #pragma unroll
        for (int kk = 0; kk < 4; kk++) {
            uint32_t oA = ((cA + 2*kk) ^ sw) * 16;
            uint32_t oB = ((cB + 2*kk) ^ sw) * 16;
            uint32_t ua[4];
            ldsm_x4(ua[0], ua[1], ua[2], ua[3], aU + oA);

            // attn write: fragments -> float2 * I
            {
                int c = kk * 16 + tig * 2;
                float2 f0 = __half22float2(*(__half2*)&ua[0]);   // (r0, c)
                float2 f1 = __half22float2(*(__half2*)&ua[1]);   // (r1, c)
                float2 f2 = __half22float2(*(__half2*)&ua[2]);   // (r0, c+8)
                float2 f3 = __half22float2(*(__half2*)&ua[3]);   // (r1, c+8)
                size_t ro0 = ((size_t)b * L_ + m0 + r0) * L_ + n0;
                size_t ro1 = ((size_t)b * L_ + m0 + r1) * L_ + n0;
                *(float2*)(attn + ro0 + c)     = make_float2(f0.x * I0, f0.y * I0);
                *(float2*)(attn + ro1 + c)     = make_float2(f1.x * I1, f1.y * I1);
                *(float2*)(attn + ro0 + c + 8) = make_float2(f2.x * I0, f2.y * I0);
                *(float2*)(attn + ro1 + c + 8) = make_float2(f3.x * I1, f3.y * I1);
            }

            #pragma unroll
            for (int g = 0; g < 4; g++) {
                uint32_t vf[4];
                ldsm_x4(vf[0], vf[1], vf[2], vf[3], vb_base + rowBoff[g] + oB);
                mma_f16(accO[g*2],   ua[0], ua[1], ua[2], ua[3], vf[0], vf[1]);
                mma_f16(accO[g*2+1], ua[0], ua[1], ua[2], ua[3], vf[2], vf[3]);
            }
        }
    }

    // ---- out epilogue: atomicAdd partial O * I (out pre-zeroed)
    #pragma unroll
    for (int j = 0; j < 8; j++) {
        int c = j*8 + tig*2;
        float* o0 = out + ((size_t)b * L_ + m0 + r0) * D_ + c;
        float* o1 = out + ((size_t)b * L_ + m0 + r1) * D_ + c;
        atomicAdd(o0,     accO[j][0] * I0);
        atomicAdd(o0 + 1, accO[j][1] * I0);
        atomicAdd(o1,     accO[j][2] * I1);
        atomicAdd(o1 + 1, accO[j][3] * I1);
    }
}

// ----------------------------------------------------------------- launcher
extern "C" void kernel_launch(void* const* d_in, const int* in_sizes, int n_in,
                              void* d_out, int out_size) {
    const float* q = (const float*)d_in[0];
    const float* k = (const float*)d_in[1];
    const float* v = (const float*)d_in[2];
    const int* mask = (const int*)d_in[3];
    float* out  = (float*)d_out;
    float* attn = out + (size_t)B_ * L_ * D_;

    cudaFuncSetAttribute(scores_kernel, cudaFuncAttributeMaxDynamicSharedMemorySize, 32768);
    cudaFuncSetAttribute(av_kernel,     cudaFuncAttributeMaxDynamicSharedMemorySize, 33024);

    // prep on the origin (default) stream
    int n = NE;
    prep_qk<<<dim3((n/2 + 255) / 256, 2), 256>>>(q, k, n);
    vtrans_kernel<<<dim3(L_/32, 2, B_), dim3(32, 8)>>>(v);
    cudaMemsetAsync(out, 0, (size_t)NE * sizeof(float));

    // fork two streams: S1 = scores+combine, S2 = av; per-chunk events chain them.
    cudaStream_t s1, s2;
    cudaStreamCreateWithFlags(&s1, cudaStreamNonBlocking);
    cudaStreamCreateWithFlags(&s2, cudaStreamNonBlocking);
    cudaEvent_t evP, evF, evS[NCH];
    cudaEventCreateWithFlags(&evP, cudaEventDisableTiming);
    cudaEventCreateWithFlags(&evF, cudaEventDisableTiming);
    for (int c = 0; c < NCH; c++) cudaEventCreateWithFlags(&evS[c], cudaEventDisableTiming);

    cudaEventRecord(evP, 0);
    cudaStreamWaitEvent(s1, evP, 0);
    cudaStreamWaitEvent(s2, evP, 0);

    for (int c = 0; c < NCH; c++) {
        int b0 = c * BCH;
        scores_kernel<<<dim3(L_/64, BCH, 2), 128, 32768, s1>>>(mask, b0);
        combine_kernel<<<(BCH * L_) / 256, 256, 0, s1>>>(b0);
        cudaEventRecord(evS[c], s1);
        cudaStreamWaitEvent(s2, evS[c], 0);
        av_kernel<<<dim3(L_/64, BCH, 2), 128, 33024, s2>>>(attn, out, b0);
    }

    cudaEventRecord(evF, s2);
    cudaStreamWaitEvent((cudaStream_t)0, evF, 0);   // rejoin origin stream

    // host-side handles: destroying after the waits are enqueued is safe
    // (capture has recorded the dependencies; these are host objects only)
    cudaStreamDestroy(s1);
    cudaStreamDestroy(s2);
    cudaEventDestroy(evP);
    cudaEventDestroy(evF);
    for (int c = 0; c < NCH; c++) cudaEventDestroy(evS[c]);
}

// round 15
// speedup vs baseline: 1.2713x; 1.2713x over previous
#include <cuda_runtime.h>
#include <cuda_fp16.h>
#include <cstdint>

#define B_ 16
#define L_ 2048
#define D_ 64
#define NE (B_*L_*D_)
#define CE 0.18033688011112042f     // (1/8)*log2(e)

// device scratch (no allocation)
__device__ __half g_Qf[NE], g_Kf[NE];                 // fp16 Q, K [b][row][d]
__device__ __half g_VT[NE];                           // fp16 V transposed [b][d][k]
__device__ __half g_u[(size_t)B_*L_*L_];              // u, tile-blocked swizzled 8KB tiles
__device__ float2 g_Psum[2*B_*L_];                    // per-z partial (sum_all, sum_unmasked)

// ---------------------------------------------------------------- helpers
__device__ __forceinline__ uint32_t smem_u32(const void* p) {
    return (uint32_t)__cvta_generic_to_shared(p);
}
__device__ __forceinline__ void cp16(uint32_t dst, const void* src) {
    asm volatile("cp.async.cg.shared.global [%0], [%1], 16;" :: "r"(dst), "l"(src));
}
__device__ __forceinline__ void cp_commit() { asm volatile("cp.async.commit_group;"); }
__device__ __forceinline__ void cp_wait0()  { asm volatile("cp.async.wait_group 0;"); }

__device__ __forceinline__ void ldsm_x4(uint32_t& r0, uint32_t& r1, uint32_t& r2, uint32_t& r3,
                                        uint32_t addr) {
    asm volatile("ldmatrix.sync.aligned.m8n8.x4.shared.b16 {%0,%1,%2,%3}, [%4];"
                 : "=r"(r0), "=r"(r1), "=r"(r2), "=r"(r3) : "r"(addr));
}
__device__ __forceinline__ void mma_f16(float* c,
                                        uint32_t a0, uint32_t a1, uint32_t a2, uint32_t a3,
                                        uint32_t b0, uint32_t b1) {
    asm volatile(
        "mma.sync.aligned.m16n8k16.row.col.f32.f16.f16.f32 "
        "{%0,%1,%2,%3}, {%4,%5,%6,%7}, {%8,%9}, {%0,%1,%2,%3};\n"
        : "+f"(c[0]), "+f"(c[1]), "+f"(c[2]), "+f"(c[3])
        : "r"(a0), "r"(a1), "r"(a2), "r"(a3), "r"(b0), "r"(b1));
}

// ---------------------------------------------------------------- K0a: Q/K -> fp16
__global__ __launch_bounds__(256) void prep_qk(const float* __restrict__ q,
                                               const float* __restrict__ k, int n) {
    int i = (blockIdx.x * blockDim.x + threadIdx.x) * 2;
    const float* src = blockIdx.y ? k : q;
    __half* dst = blockIdx.y ? g_Kf : g_Qf;
    if (i < n) {
        float2 x = *(const float2*)(src + i);
        *(__half2*)(dst + i) = __floats2half2_rn(x.x, x.y);
    }
}

// ---------------------------------------------------------------- K0b: V transpose -> [b][d][k] fp16
__global__ __launch_bounds__(256) void vtrans_kernel(const float* __restrict__ v) {
    __shared__ float t[32][33];
    int b = blockIdx.z, d0 = blockIdx.y * 32, k0 = blockIdx.x * 32;
    int tx = threadIdx.x, ty = threadIdx.y;   // block (32,8)
    #pragma unroll
    for (int j = 0; j < 32; j += 8)
        t[ty + j][tx] = v[((size_t)b * L_ + k0 + ty + j) * D_ + d0 + tx];
    __syncthreads();
    #pragma unroll
    for (int j = 0; j < 32; j += 8) {
        int d = d0 + ty + j;
        g_VT[((size_t)b * D_ + d) * L_ + k0 + tx] = __float2half_rn(t[tx][ty + j]);
    }
}

// ---------------- K1: fp16 scores GEMM + exp + mask + partial row sums (split-K z=2)
// grid (L/64, B, 2), block 128 (4 warps x 16 rows). Dyn smem 32768B.
// Each z handles 16 k-tiles. layout: QF 0, K[d] 8192+d*8192, US 24576
__global__ __launch_bounds__(128, 5) void scores_kernel(const int* __restrict__ mask) {
    extern __shared__ char smem[];
    const int QF = 0, KB0 = 8192, US = 24576;
    int b = blockIdx.y, m0 = blockIdx.x * 64, z = blockIdx.z, tid = threadIdx.x;
    int warp = tid >> 5, lane = tid & 31, gid = lane >> 2, tig = lane & 3;
    uint32_t sm = smem_u32(smem);
    int kt0 = z * 16;

    // prologue: Q + K(kt0)
    {
        const __half* qsrc = g_Qf + ((size_t)b * L_ + m0) * D_;
        const __half* ksrc = g_Kf + ((size_t)b * L_ + kt0 * 64) * D_;
        #pragma unroll
        for (int it = 0; it < 4; it++) {
            int i = tid + it * 128, r = i >> 3, c = i & 7;
            uint32_t o = r * 128 + ((c ^ (r & 7)) * 16);
            cp16(sm + QF + o, qsrc + r * 64 + c * 8);
            cp16(sm + KB0 + o, ksrc + r * 64 + c * 8);
        }
        cp_commit();
    }

    uint32_t sw = lane & 7;
    uint32_t cA = lane >> 4;            // 0/1
    uint32_t cB = (lane >> 3) & 1;      // 0/1
    int rA = warp * 16 + (lane & 15);
    uint32_t aQ = sm + QF + rA * 128;
    uint32_t rowBoff[4];
    #pragma unroll
    for (int g = 0; g < 4; g++)
        rowBoff[g] = (uint32_t)((g * 16 + ((lane >> 4) & 1) * 8 + (lane & 7)) * 128);

    int r0 = warp * 16 + gid, r1 = r0 + 8;
    const int* mrow0 = mask + ((size_t)(b * L_ + m0 + r0)) * L_ + tig * 2;
    const int* mrow1 = mask + ((size_t)(b * L_ + m0 + r1)) * L_ + tig * 2;

    // u staging addresses (swizzled within the 8KB tile)
    char* usr0 = smem + US + r0 * 128 + tig * 4;
    char* usr1 = smem + US + r1 * 128 + tig * 4;
    int swr0 = r0 & 7, swr1 = r1 & 7;
    uint4* gUrow = (uint4*)(g_u + (((size_t)b * 32 + (m0 >> 6)) * 32) * 4096);

    float rsa0 = 0.f, rsa1 = 0.f, rsu0 = 0.f, rsu1 = 0.f;

    for (int t = 0; t < 16; t++) {
        int kt = kt0 + t;
        int d = t & 1, n0 = kt * 64;
        cp_wait0();
        __syncthreads();

        // mask prefetch into registers (latency covered by scores GEMM)
        int2 mk0[8], mk1[8];
        #pragma unroll
        for (int j = 0; j < 8; j++) {
            mk0[j] = __ldg((const int2*)(mrow0 + n0 + j*8));
            mk1[j] = __ldg((const int2*)(mrow1 + n0 + j*8));
        }

        if (t < 15) {               // prefetch K(kt+1)
            int d2 = (t + 1) & 1, n2 = (kt + 1) * 64;
            const __half* ksrc = g_Kf + ((size_t)b * L_ + n2) * D_;
            #pragma unroll
            for (int it = 0; it < 4; it++) {
                int i = tid + it * 128, r = i >> 3, c = i & 7;
                uint32_t o = r * 128 + ((c ^ (r & 7)) * 16);
                cp16(sm + KB0 + d2 * 8192 + o, ksrc + r * 64 + c * 8);
            }
            cp_commit();
        }

        // ---- scores: S(16x64) = Q_warp(16x64) · K^T(64x64), single fp16 GEMM
        float accS[8][4];
        #pragma unroll
        for (int j = 0; j < 8; j++)
            #pragma unroll
            for (int x = 0; x < 4; x++) accS[j][x] = 0.f;

        uint32_t kb_base = sm + KB0 + d * 8192;
        #pragma unroll
        for (int kk = 0; kk < 4; kk++) {
            uint32_t oA = ((cA + 2*kk) ^ sw) * 16;
            uint32_t oB = ((cB + 2*kk) ^ sw) * 16;
            uint32_t a[4];
            ldsm_x4(a[0], a[1], a[2], a[3], aQ + oA);
            #pragma unroll
            for (int g = 0; g < 4; g++) {
                uint32_t bfr[4];
                ldsm_x4(bfr[0], bfr[1], bfr[2], bfr[3], kb_base + rowBoff[g] + oB);
                mma_f16(accS[g*2],   a[0], a[1], a[2], a[3], bfr[0], bfr[1]);
                mma_f16(accS[g*2+1], a[0], a[1], a[2], a[3], bfr[2], bfr[3]);
            }
        }

        // ---- epilogue: exp, mask, sums, STS u into swizzled staging tile
        #pragma unroll
        for (int j = 0; j < 8; j++) {
            float e0 = exp2f(accS[j][0] * CE);
            float e1 = exp2f(accS[j][1] * CE);
            float e2 = exp2f(accS[j][2] * CE);
            float e3 = exp2f(accS[j][3] * CE);
            rsa0 += e0 + e1;
            rsa1 += e2 + e3;
            float a0 = mk0[j].x ? 0.f : e0;
            float a1 = mk0[j].y ? 0.f : e1;
            float a2 = mk1[j].x ? 0.f : e2;
            float a3 = mk1[j].y ? 0.f : e3;
            rsu0 += a0 + a1;
            rsu1 += a2 + a3;
            *(__half2*)(usr0 + ((j ^ swr0) * 16)) = __floats2half2_rn(a0, a1);
            *(__half2*)(usr1 + ((j ^ swr1) * 16)) = __floats2half2_rn(a2, a3);
        }
        __syncthreads();   // staging tile complete

        // ---- coalesced STG.128 of the 8KB swizzled tile
        {
            uint4* gU = gUrow + (size_t)kt * 512;
            const uint4* sU = (const uint4*)(smem + US);
            #pragma unroll
            for (int it = 0; it < 4; it++)
                gU[tid + it * 128] = sU[tid + it * 128];
        }
    }

    // ---- partial sums: butterfly over tig lanes, write per-z
    #pragma unroll
    for (int o = 1; o <= 2; o <<= 1) {
        rsa0 += __shfl_xor_sync(0xffffffffu, rsa0, o);
        rsa1 += __shfl_xor_sync(0xffffffffu, rsa1, o);
        rsu0 += __shfl_xor_sync(0xffffffffu, rsu0, o);
        rsu1 += __shfl_xor_sync(0xffffffffu, rsu1, o);
    }
    if (tig == 0) {
        g_Psum[z * (B_*L_) + b * L_ + m0 + r0] = make_float2(rsa0, rsu0);
        g_Psum[z * (B_*L_) + b * L_ + m0 + r1] = make_float2(rsa1, rsu1);
    }
}

// ---------------- K2: read tile-blocked u -> attn=u*I write + O = u@V*I
// Combine fused: I computed from g_Psum partials at kernel start.
// grid (L/64, B), block 128. Dyn smem 33024B (6 CTAs/SM).
// layout: U[d] 0+d*8192, V[d] 16384+d*8192, SI 32768
__global__ __launch_bounds__(128, 6) void av_kernel(float* __restrict__ attn,
                                                    float* __restrict__ out) {
    extern __shared__ char smem[];
    const int UB = 0, VB = 16384, SI = 32768;
    int b = blockIdx.y, m0 = blockIdx.x * 64, tid = threadIdx.x;
    int warp = tid >> 5, lane = tid & 31, gid = lane >> 2, tig = lane & 3;
    uint32_t sm = smem_u32(smem);
    float* sI = (float*)(smem + SI);

    // fused combine: I = 1/(su + 1e-8*sa) from the two split-K partials
    if (tid < 64) {
        int row = b * L_ + m0 + tid;
        float2 p0 = g_Psum[row];
        float2 p1 = g_Psum[B_*L_ + row];
        sI[tid] = 1.f / ((p0.y + p1.y) + 1e-8f * (p0.x + p1.x));
    }

    const uint4* gUrow = (const uint4*)(g_u + (((size_t)b * 32 + (m0 >> 6)) * 32) * 4096);

    // prologue: U(0) linear copy, V(0)
    {
        #pragma unroll
        for (int it = 0; it < 4; it++)
            cp16(sm + UB + (tid + it * 128) * 16, gUrow + tid + it * 128);
        #pragma unroll
        for (int it = 0; it < 4; it++) {
            int i = tid + it * 128, r = i >> 3, c = i & 7;
            uint32_t o = r * 128 + ((c ^ (r & 7)) * 16);
            cp16(sm + VB + o, g_VT + ((size_t)b * D_ + r) * L_ + c * 8);
        }
        cp_commit();
    }

    uint32_t sw = lane & 7;
    uint32_t cA = lane >> 4;
    uint32_t cB = (lane >> 3) & 1;
    int rA = warp * 16 + (lane & 15);
    uint32_t rowBoff[4];
    #pragma unroll
    for (int g = 0; g < 4; g++)
        rowBoff[g] = (uint32_t)((g * 16 + ((lane >> 4) & 1) * 8 + (lane & 7)) * 128);

    int r0 = warp * 16 + gid, r1 = r0 + 8;

    float accO[8][4];
    #pragma unroll
    for (int j = 0; j < 8; j++)
        #pragma unroll
        for (int x = 0; x < 4; x++) accO[j][x] = 0.f;

    float I0 = 0.f, I1 = 0.f;

    for (int kt = 0; kt < 32; kt++) {
        int d = kt & 1, n0 = kt * 64;
        cp_wait0();
        __syncthreads();
        if (kt == 0) { I0 = sI[r0]; I1 = sI[r1]; }

        if (kt < 31) {              // prefetch U,V(kt+1)
            int d2 = (kt + 1) & 1, n2 = (kt + 1) * 64;
            const uint4* ub = gUrow + (size_t)(kt + 1) * 512;
            #pragma unroll
            for (int it = 0; it < 4; it++)
                cp16(sm + UB + d2 * 8192 + (tid + it * 128) * 16, ub + tid + it * 128);
            #pragma unroll
            for (int it = 0; it < 4; it++) {
                int i = tid + it * 128, r = i >> 3, c = i & 7;
                uint32_t o = r * 128 + ((c ^ (r & 7)) * 16);
                cp16(sm + VB + d2 * 8192 + o, g_VT + ((size_t)b * D_ + r) * L_ + n2 + c * 8);
            }
            cp_commit();
        }

        uint32_t aU = sm + UB + d * 8192 + rA * 128;
        uint32_t vb_base = sm + VB + d * 8192;

        #pragma unroll
        for (int kk = 0; kk < 4; kk++) {
            uint32_t oA = ((cA + 2*kk) ^ sw) * 16;
            uint32_t oB = ((cB + 2*kk) ^ sw) * 16;
            uint32_t ua[4];
            ldsm_x4(ua[0], ua[1], ua[2], ua[3], aU + oA);

            // attn write: fragments -> float2 * I
            {
                int c = kk * 16 + tig * 2;
                float2 f0 = __half22float2(*(__half2*)&ua[0]);   // (r0, c)
                float2 f1 = __half22float2(*(__half2*)&ua[1]);   // (r1, c)
                float2 f2 = __half22float2(*(__half2*)&ua[2]);   // (r0, c+8)
                float2 f3 = __half22float2(*(__half2*)&ua[3]);   // (r1, c+8)
                size_t ro0 = ((size_t)b * L_ + m0 + r0) * L_ + n0;
                size_t ro1 = ((size_t)b * L_ + m0 + r1) * L_ + n0;
                *(float2*)(attn + ro0 + c)     = make_float2(f0.x * I0, f0.y * I0);
                *(float2*)(attn + ro1 + c)     = make_float2(f1.x * I1, f1.y * I1);
                *(float2*)(attn + ro0 + c + 8) = make_float2(f2.x * I0, f2.y * I0);
                *(float2*)(attn + ro1 + c + 8) = make_float2(f3.x * I1, f3.y * I1);
            }

            #pragma unroll
            for (int g = 0; g < 4; g++) {
                uint32_t vf[4];
                ldsm_x4(vf[0], vf[1], vf[2], vf[3], vb_base + rowBoff[g] + oB);
                mma_f16(accO[g*2],   ua[0], ua[1], ua[2], ua[3], vf[0], vf[1]);
                mma_f16(accO[g*2+1], ua[0], ua[1], ua[2], ua[3], vf[2], vf[3]);
            }
        }
    }

    // ---- out epilogue: O = O_u * I
    #pragma unroll
    for (int j = 0; j < 8; j++) {
        int c = j*8 + tig*2;
        *(float2*)(out + ((size_t)b * L_ + m0 + r0) * D_ + c) =
            make_float2(accO[j][0] * I0, accO[j][1] * I0);
        *(float2*)(out + ((size_t)b * L_ + m0 + r1) * D_ + c) =
            make_float2(accO[j][2] * I1, accO[j][3] * I1);
    }
}

// ----------------------------------------------------------------- launcher
extern "C" void kernel_launch(void* const* d_in, const int* in_sizes, int n_in,
                              void* d_out, int out_size) {
    const float* q = (const float*)d_in[0];
    const float* k = (const float*)d_in[1];
    const float* v = (const float*)d_in[2];
    const int* mask = (const int*)d_in[3];
    float* out  = (float*)d_out;
    float* attn = out + (size_t)B_ * L_ * D_;

    cudaFuncSetAttribute(scores_kernel, cudaFuncAttributeMaxDynamicSharedMemorySize, 32768);
    cudaFuncSetAttribute(av_kernel,     cudaFuncAttributeMaxDynamicSharedMemorySize, 33024);

    int n = NE;
    prep_qk<<<dim3((n/2 + 255) / 256, 2), 256>>>(q, k, n);
    vtrans_kernel<<<dim3(L_/32, 2, B_), dim3(32, 8)>>>(v);

    scores_kernel<<<dim3(L_/64, B_, 2), 128, 32768>>>(mask);
    av_kernel<<<dim3(L_/64, B_), 128, 33024>>>(attn, out);
}

// round 16
// speedup vs baseline: 1.5158x; 1.1923x over previous
#include <cuda_runtime.h>
#include <cuda_fp16.h>
#include <cstdint>

#define B_ 16
#define L_ 2048
#define D_ 64
#define NE (B_*L_*D_)
#define CE 0.18033688011112042f     // (1/8)*log2(e)

// device scratch (no allocation)
__device__ __half g_Qf[NE], g_Kf[NE];                 // fp16 Q, K [b][row][d]
__device__ __half g_VT[NE];                           // fp16 V transposed [b][d][k]
__device__ __half g_u[(size_t)B_*L_*L_];              // u, tile-blocked swizzled 8KB tiles
__device__ float2 g_Psum[2*B_*L_];                    // per-z partial (sum_all, sum_unmasked)

// ---------------------------------------------------------------- helpers
__device__ __forceinline__ uint32_t smem_u32(const void* p) {
    return (uint32_t)__cvta_generic_to_shared(p);
}
__device__ __forceinline__ void cp16(uint32_t dst, const void* src) {
    asm volatile("cp.async.cg.shared.global [%0], [%1], 16;" :: "r"(dst), "l"(src));
}
__device__ __forceinline__ void cp_commit() { asm volatile("cp.async.commit_group;"); }
__device__ __forceinline__ void cp_wait0()  { asm volatile("cp.async.wait_group 0;"); }

__device__ __forceinline__ void ldsm_x4(uint32_t& r0, uint32_t& r1, uint32_t& r2, uint32_t& r3,
                                        uint32_t addr) {
    asm volatile("ldmatrix.sync.aligned.m8n8.x4.shared.b16 {%0,%1,%2,%3}, [%4];"
                 : "=r"(r0), "=r"(r1), "=r"(r2), "=r"(r3) : "r"(addr));
}
__device__ __forceinline__ void mma_f16(float* c,
                                        uint32_t a0, uint32_t a1, uint32_t a2, uint32_t a3,
                                        uint32_t b0, uint32_t b1) {
    asm volatile(
        "mma.sync.aligned.m16n8k16.row.col.f32.f16.f16.f32 "
        "{%0,%1,%2,%3}, {%4,%5,%6,%7}, {%8,%9}, {%0,%1,%2,%3};\n"
        : "+f"(c[0]), "+f"(c[1]), "+f"(c[2]), "+f"(c[3])
        : "r"(a0), "r"(a1), "r"(a2), "r"(a3), "r"(b0), "r"(b1));
}

// ---------------------------------------------------------------- K0a: Q/K -> fp16
__global__ __launch_bounds__(256) void prep_qk(const float* __restrict__ q,
                                               const float* __restrict__ k, int n) {
    int i = (blockIdx.x * blockDim.x + threadIdx.x) * 2;
    const float* src = blockIdx.y ? k : q;
    __half* dst = blockIdx.y ? g_Kf : g_Qf;
    if (i < n) {
        float2 x = *(const float2*)(src + i);
        *(__half2*)(dst + i) = __floats2half2_rn(x.x, x.y);
    }
}

// ---------------------------------------------------------------- K0b: V transpose -> [b][d][k] fp16
__global__ __launch_bounds__(256) void vtrans_kernel(const float* __restrict__ v) {
    __shared__ float t[32][33];
    int b = blockIdx.z, d0 = blockIdx.y * 32, k0 = blockIdx.x * 32;
    int tx = threadIdx.x, ty = threadIdx.y;   // block (32,8)
    #pragma unroll
    for (int j = 0; j < 32; j += 8)
        t[ty + j][tx] = v[((size_t)b * L_ + k0 + ty + j) * D_ + d0 + tx];
    __syncthreads();
    #pragma unroll
    for (int j = 0; j < 32; j += 8) {
        int d = d0 + ty + j;
        g_VT[((size_t)b * D_ + d) * L_ + k0 + tx] = __float2half_rn(t[tx][ty + j]);
    }
}

// ---------------- K1: fp16 scores GEMM + exp + mask + partial row sums (split-K z=2)
// grid (L/64, B, 2), block 128 (4 warps x 16 rows). Dyn smem 32768B.
// Each z handles 16 k-tiles. layout: QF 0, K[d] 8192+d*8192, US 24576
__global__ __launch_bounds__(128, 4) void scores_kernel(const int* __restrict__ mask) {
    extern __shared__ char smem[];
    const int QF = 0, KB0 = 8192, US = 24576;
    int b = blockIdx.y, m0 = blockIdx.x * 64, z = blockIdx.z, tid = threadIdx.x;
    int warp = tid >> 5, lane = tid & 31, gid = lane >> 2, tig = lane & 3;
    uint32_t sm = smem_u32(smem);
    int kt0 = z * 16;

    // prologue: Q + K(kt0)
    {
        const __half* qsrc = g_Qf + ((size_t)b * L_ + m0) * D_;
        const __half* ksrc = g_Kf + ((size_t)b * L_ + kt0 * 64) * D_;
        #pragma unroll
        for (int it = 0; it < 4; it++) {
            int i = tid + it * 128, r = i >> 3, c = i & 7;
            uint32_t o = r * 128 + ((c ^ (r & 7)) * 16);
            cp16(sm + QF + o, qsrc + r * 64 + c * 8);
            cp16(sm + KB0 + o, ksrc + r * 64 + c * 8);
        }
        cp_commit();
    }

    uint32_t sw = lane & 7;
    uint32_t cA = lane >> 4;            // 0/1
    uint32_t cB = (lane >> 3) & 1;      // 0/1
    int rA = warp * 16 + (lane & 15);
    uint32_t aQ = sm + QF + rA * 128;
    uint32_t rowBoff[4];
    #pragma unroll
    for (int g = 0; g < 4; g++)
        rowBoff[g] = (uint32_t)((g * 16 + ((lane >> 4) & 1) * 8 + (lane & 7)) * 128);

    int r0 = warp * 16 + gid, r1 = r0 + 8;
    const int* mrow0 = mask + ((size_t)(b * L_ + m0 + r0)) * L_ + tig * 2;
    const int* mrow1 = mask + ((size_t)(b * L_ + m0 + r1)) * L_ + tig * 2;

    // u staging addresses (swizzled within the 8KB tile)
    char* usr0 = smem + US + r0 * 128 + tig * 4;
    char* usr1 = smem + US + r1 * 128 + tig * 4;
    int swr0 = r0 & 7, swr1 = r1 & 7;
    uint4* gUrow = (uint4*)(g_u + (((size_t)b * 32 + (m0 >> 6)) * 32) * 4096);

    float rsa0 = 0.f, rsa1 = 0.f, rsu0 = 0.f, rsu1 = 0.f;

    for (int t = 0; t < 16; t++) {
        int kt = kt0 + t;
        int d = t & 1, n0 = kt * 64;
        cp_wait0();
        __syncthreads();

        // mask prefetch into registers (latency covered by scores GEMM)
        int2 mk0[8], mk1[8];
        #pragma unroll
        for (int j = 0; j < 8; j++) {
            mk0[j] = __ldg((const int2*)(mrow0 + n0 + j*8));
            mk1[j] = __ldg((const int2*)(mrow1 + n0 + j*8));
        }

        if (t < 15) {               // prefetch K(kt+1)
            int d2 = (t + 1) & 1, n2 = (kt + 1) * 64;
            const __half* ksrc = g_Kf + ((size_t)b * L_ + n2) * D_;
            #pragma unroll
            for (int it = 0; it < 4; it++) {
                int i = tid + it * 128, r = i >> 3, c = i & 7;
                uint32_t o = r * 128 + ((c ^ (r & 7)) * 16);
                cp16(sm + KB0 + d2 * 8192 + o, ksrc + r * 64 + c * 8);
            }
            cp_commit();
        }

        // ---- scores: S(16x64) = Q_warp(16x64) · K^T(64x64), single fp16 GEMM
        float accS[8][4];
        #pragma unroll
        for (int j = 0; j < 8; j++)
            #pragma unroll
            for (int x = 0; x < 4; x++) accS[j][x] = 0.f;

        uint32_t kb_base = sm + KB0 + d * 8192;
        #pragma unroll
        for (int kk = 0; kk < 4; kk++) {
            uint32_t oA = ((cA + 2*kk) ^ sw) * 16;
            uint32_t oB = ((cB + 2*kk) ^ sw) * 16;
            uint32_t a[4];
            ldsm_x4(a[0], a[1], a[2], a[3], aQ + oA);
            #pragma unroll
            for (int g = 0; g < 4; g++) {
                uint32_t bfr[4];
                ldsm_x4(bfr[0], bfr[1], bfr[2], bfr[3], kb_base + rowBoff[g] + oB);
                mma_f16(accS[g*2],   a[0], a[1], a[2], a[3], bfr[0], bfr[1]);
                mma_f16(accS[g*2+1], a[0], a[1], a[2], a[3], bfr[2], bfr[3]);
            }
        }

        // ---- epilogue: exp, mask, sums, STS u into swizzled staging tile
        #pragma unroll
        for (int j = 0; j < 8; j++) {
            float e0 = exp2f(accS[j][0] * CE);
            float e1 = exp2f(accS[j][1] * CE);
            float e2 = exp2f(accS[j][2] * CE);
            float e3 = exp2f(accS[j][3] * CE);
            rsa0 += e0 + e1;
            rsa1 += e2 + e3;
            float a0 = mk0[j].x ? 0.f : e0;
            float a1 = mk0[j].y ? 0.f : e1;
            float a2 = mk1[j].x ? 0.f : e2;
            float a3 = mk1[j].y ? 0.f : e3;
            rsu0 += a0 + a1;
            rsu1 += a2 + a3;
            *(__half2*)(usr0 + ((j ^ swr0) * 16)) = __floats2half2_rn(a0, a1);
            *(__half2*)(usr1 + ((j ^ swr1) * 16)) = __floats2half2_rn(a2, a3);
        }
        __syncthreads();   // staging tile complete

        // ---- coalesced streaming STG.128 of the 8KB swizzled tile
        {
            uint4* gU = gUrow + (size_t)kt * 512;
            const uint4* sU = (const uint4*)(smem + US);
            #pragma unroll
            for (int it = 0; it < 4; it++)
                __stcs(gU + tid + it * 128, sU[tid + it * 128]);
        }
    }

    // ---- partial sums: butterfly over tig lanes, write per-z
    #pragma unroll
    for (int o = 1; o <= 2; o <<= 1) {
        rsa0 += __shfl_xor_sync(0xffffffffu, rsa0, o);
        rsa1 += __shfl_xor_sync(0xffffffffu, rsa1, o);
        rsu0 += __shfl_xor_sync(0xffffffffu, rsu0, o);
        rsu1 += __shfl_xor_sync(0xffffffffu, rsu1, o);
    }
    if (tig == 0) {
        g_Psum[z * (B_*L_) + b * L_ + m0 + r0] = make_float2(rsa0, rsu0);
        g_Psum[z * (B_*L_) + b * L_ + m0 + r1] = make_float2(rsa1, rsu1);
    }
}

// ---------------- K2: read tile-blocked u -> attn=u*I write + O += u@V*I (split-K z=2)
// Combine fused: I computed from both g_Psum partials at kernel start.
// grid (L/64, B, 2), block 128. Dyn smem 33024B. atomicAdd into zeroed out.
// layout: U[d] 0+d*8192, V[d] 16384+d*8192, SI 32768
__global__ __launch_bounds__(128, 6) void av_kernel(float* __restrict__ attn,
                                                    float* __restrict__ out) {
    extern __shared__ char smem[];
    const int UB = 0, VB = 16384, SI = 32768;
    int b = blockIdx.y, m0 = blockIdx.x * 64, z = blockIdx.z, tid = threadIdx.x;
    int warp = tid >> 5, lane = tid & 31, gid = lane >> 2, tig = lane & 3;
    uint32_t sm = smem_u32(smem);
    float* sI = (float*)(smem + SI);
    int kt0 = z * 16;

    // fused combine: I = 1/(su + 1e-8*sa) from the two split-K partials
    if (tid < 64) {
        int row = b * L_ + m0 + tid;
        float2 p0 = g_Psum[row];
        float2 p1 = g_Psum[B_*L_ + row];
        sI[tid] = 1.f / ((p0.y + p1.y) + 1e-8f * (p0.x + p1.x));
    }

    const uint4* gUrow = (const uint4*)(g_u + (((size_t)b * 32 + (m0 >> 6)) * 32) * 4096);

    // prologue: U(kt0) linear copy, V(kt0)
    {
        const uint4* ub = gUrow + (size_t)kt0 * 512;
        #pragma unroll
        for (int it = 0; it < 4; it++)
            cp16(sm + UB + (tid + it * 128) * 16, ub + tid + it * 128);
        #pragma unroll
        for (int it = 0; it < 4; it++) {
            int i = tid + it * 128, r = i >> 3, c = i & 7;
            uint32_t o = r * 128 + ((c ^ (r & 7)) * 16);
            cp16(sm + VB + o, g_VT + ((size_t)b * D_ + r) * L_ + kt0 * 64 + c * 8);
        }
        cp_commit();
    }

    uint32_t sw = lane & 7;
    uint32_t cA = lane >> 4;
    uint32_t cB = (lane >> 3) & 1;
    int rA = warp * 16 + (lane & 15);
    uint32_t rowBoff[4];
    #pragma unroll
    for (int g = 0; g < 4; g++)
        rowBoff[g] = (uint32_t)((g * 16 + ((lane >> 4) & 1) * 8 + (lane & 7)) * 128);

    int r0 = warp * 16 + gid, r1 = r0 + 8;

    float accO[8][4];
    #pragma unroll
    for (int j = 0; j < 8; j++)
        #pragma unroll
        for (int x = 0; x < 4; x++) accO[j][x] = 0.f;

    float I0 = 0.f, I1 = 0.f;

    for (int t = 0; t < 16; t++) {
        int kt = kt0 + t;
        int d = t & 1, n0 = kt * 64;
        cp_wait0();
        __syncthreads();
        if (t == 0) { I0 = sI[r0]; I1 = sI[r1]; }

        if (t < 15) {               // prefetch U,V(kt+1)
            int d2 = (t + 1) & 1, n2 = (kt + 1) * 64;
            const uint4* ub = gUrow + (size_t)(kt + 1) * 512;
            #pragma unroll
            for (int it = 0; it < 4; it++)
                cp16(sm + UB + d2 * 8192 + (tid + it * 128) * 16, ub + tid + it * 128);
            #pragma unroll
            for (int it = 0; it < 4; it++) {
                int i = tid + it * 128, r = i >> 3, c = i & 7;
                uint32_t o = r * 128 + ((c ^ (r & 7)) * 16);
                cp16(sm + VB + d2 * 8192 + o, g_VT + ((size_t)b * D_ + r) * L_ + n2 + c * 8);
            }
            cp_commit();
        }

        uint32_t aU = sm + UB + d * 8192 + rA * 128;
        uint32_t vb_base = sm + VB + d * 8192;

        #pragma unroll
        for (int kk = 0; kk < 4; kk++) {
            uint32_t oA = ((cA + 2*kk) ^ sw) * 16;
            uint32_t oB = ((cB + 2*kk) ^ sw) * 16;
            uint32_t ua[4];
            ldsm_x4(ua[0], ua[1], ua[2], ua[3], aU + oA);

            // attn write: fragments -> float2 * I (streaming stores)
            {
                int c = kk * 16 + tig * 2;
                float2 f0 = __half22float2(*(__half2*)&ua[0]);   // (r0, c)
                float2 f1 = __half22float2(*(__half2*)&ua[1]);   // (r1, c)
                float2 f2 = __half22float2(*(__half2*)&ua[2]);   // (r0, c+8)
                float2 f3 = __half22float2(*(__half2*)&ua[3]);   // (r1, c+8)
                size_t ro0 = ((size_t)b * L_ + m0 + r0) * L_ + n0;
                size_t ro1 = ((size_t)b * L_ + m0 + r1) * L_ + n0;
                __stcs((float2*)(attn + ro0 + c),     make_float2(f0.x * I0, f0.y * I0));
                __stcs((float2*)(attn + ro1 + c),     make_float2(f1.x * I1, f1.y * I1));
                __stcs((float2*)(attn + ro0 + c + 8), make_float2(f2.x * I0, f2.y * I0));
                __stcs((float2*)(attn + ro1 + c + 8), make_float2(f3.x * I1, f3.y * I1));
            }

            #pragma unroll
            for (int g = 0; g < 4; g++) {
                uint32_t vf[4];
                ldsm_x4(vf[0], vf[1], vf[2], vf[3], vb_base + rowBoff[g] + oB);
                mma_f16(accO[g*2],   ua[0], ua[1], ua[2], ua[3], vf[0], vf[1]);
                mma_f16(accO[g*2+1], ua[0], ua[1], ua[2], ua[3], vf[2], vf[3]);
            }
        }
    }

    // ---- out epilogue: atomicAdd partial O * I (out pre-zeroed)
    #pragma unroll
    for (int j = 0; j < 8; j++) {
        int c = j*8 + tig*2;
        float* o0 = out + ((size_t)b * L_ + m0 + r0) * D_ + c;
        float* o1 = out + ((size_t)b * L_ + m0 + r1) * D_ + c;
        atomicAdd(o0,     accO[j][0] * I0);
        atomicAdd(o0 + 1, accO[j][1] * I0);
        atomicAdd(o1,     accO[j][2] * I1);
        atomicAdd(o1 + 1, accO[j][3] * I1);
    }
}

// ----------------------------------------------------------------- launcher
extern "C" void kernel_launch(void* const* d_in, const int* in_sizes, int n_in,
                              void* d_out, int out_size) {
    const float* q = (const float*)d_in[0];
    const float* k = (const float*)d_in[1];
    const float* v = (const float*)d_in[2];
    const int* mask = (const int*)d_in[3];
    float* out  = (float*)d_out;
    float* attn = out + (size_t)B_ * L_ * D_;

    cudaFuncSetAttribute(scores_kernel, cudaFuncAttributeMaxDynamicSharedMemorySize, 32768);
    cudaFuncSetAttribute(av_kernel,     cudaFuncAttributeMaxDynamicSharedMemorySize, 33024);

    int n = NE;
    prep_qk<<<dim3((n/2 + 255) / 256, 2), 256>>>(q, k, n);
    vtrans_kernel<<<dim3(L_/32, 2, B_), dim3(32, 8)>>>(v);
    cudaMemsetAsync(out, 0, (size_t)NE * sizeof(float));

    scores_kernel<<<dim3(L_/64, B_, 2), 128, 32768>>>(mask);
    av_kernel<<<dim3(L_/64, B_, 2), 128, 33024>>>(attn, out);
}

// round 17
// speedup vs baseline: 1.5317x; 1.0105x over previous
#include <cuda_runtime.h>
#include <cuda_fp16.h>
#include <cstdint>

#define B_ 16
#define L_ 2048
#define D_ 64
#define NE (B_*L_*D_)
#define CE 0.18033688011112042f     // (1/8)*log2(e)

// device scratch (no allocation)
__device__ __half g_Qf[NE], g_Kf[NE];                 // fp16 Q, K [b][row][d]
__device__ __half g_VT[NE];                           // fp16 V transposed [b][d][k]
__device__ __half g_u[(size_t)B_*L_*L_];              // u, tile-blocked swizzled 8KB tiles
__device__ float2 g_Psum[2*B_*L_];                    // per-z partial (sum_all, sum_unmasked)

// ---------------------------------------------------------------- helpers
__device__ __forceinline__ uint32_t smem_u32(const void* p) {
    return (uint32_t)__cvta_generic_to_shared(p);
}
__device__ __forceinline__ void cp16(uint32_t dst, const void* src) {
    asm volatile("cp.async.cg.shared.global [%0], [%1], 16;" :: "r"(dst), "l"(src));
}
__device__ __forceinline__ void cp_commit() { asm volatile("cp.async.commit_group;"); }
__device__ __forceinline__ void cp_wait0()  { asm volatile("cp.async.wait_group 0;"); }

__device__ __forceinline__ void ldsm_x4(uint32_t& r0, uint32_t& r1, uint32_t& r2, uint32_t& r3,
                                        uint32_t addr) {
    asm volatile("ldmatrix.sync.aligned.m8n8.x4.shared.b16 {%0,%1,%2,%3}, [%4];"
                 : "=r"(r0), "=r"(r1), "=r"(r2), "=r"(r3) : "r"(addr));
}
__device__ __forceinline__ void mma_f16(float* c,
                                        uint32_t a0, uint32_t a1, uint32_t a2, uint32_t a3,
                                        uint32_t b0, uint32_t b1) {
    asm volatile(
        "mma.sync.aligned.m16n8k16.row.col.f32.f16.f16.f32 "
        "{%0,%1,%2,%3}, {%4,%5,%6,%7}, {%8,%9}, {%0,%1,%2,%3};\n"
        : "+f"(c[0]), "+f"(c[1]), "+f"(c[2]), "+f"(c[3])
        : "r"(a0), "r"(a1), "r"(a2), "r"(a3), "r"(b0), "r"(b1));
}

// ---------------------------------------------------------------- K0a: Q/K -> fp16
__global__ __launch_bounds__(256) void prep_qk(const float* __restrict__ q,
                                               const float* __restrict__ k, int n) {
    int i = (blockIdx.x * blockDim.x + threadIdx.x) * 2;
    const float* src = blockIdx.y ? k : q;
    __half* dst = blockIdx.y ? g_Kf : g_Qf;
    if (i < n) {
        float2 x = *(const float2*)(src + i);
        *(__half2*)(dst + i) = __floats2half2_rn(x.x, x.y);
    }
}

// ---------------------------------------------------------------- K0b: V transpose -> [b][d][k] fp16
__global__ __launch_bounds__(256) void vtrans_kernel(const float* __restrict__ v) {
    __shared__ float t[32][33];
    int b = blockIdx.z, d0 = blockIdx.y * 32, k0 = blockIdx.x * 32;
    int tx = threadIdx.x, ty = threadIdx.y;   // block (32,8)
    #pragma unroll
    for (int j = 0; j < 32; j += 8)
        t[ty + j][tx] = v[((size_t)b * L_ + k0 + ty + j) * D_ + d0 + tx];
    __syncthreads();
    #pragma unroll
    for (int j = 0; j < 32; j += 8) {
        int d = d0 + ty + j;
        g_VT[((size_t)b * D_ + d) * L_ + k0 + tx] = __float2half_rn(t[tx][ty + j]);
    }
}

// ---------------- K1: fp16 scores GEMM + exp + mask + partial row sums (split-K z=2)
// grid (L/64, B, 2), block 128 (4 warps x 16 rows). Dyn smem 32768B.
// Each z handles 16 k-tiles. layout: QF 0, K[d] 8192+d*8192, US 24576
__global__ __launch_bounds__(128, 4) void scores_kernel(const int* __restrict__ mask) {
    extern __shared__ char smem[];
    const int QF = 0, KB0 = 8192, US = 24576;
    int b = blockIdx.y, m0 = blockIdx.x * 64, z = blockIdx.z, tid = threadIdx.x;
    int warp = tid >> 5, lane = tid & 31, gid = lane >> 2, tig = lane & 3;
    uint32_t sm = smem_u32(smem);
    int kt0 = z * 16;

    // prologue: Q + K(kt0)
    {
        const __half* qsrc = g_Qf + ((size_t)b * L_ + m0) * D_;
        const __half* ksrc = g_Kf + ((size_t)b * L_ + kt0 * 64) * D_;
        #pragma unroll
        for (int it = 0; it < 4; it++) {
            int i = tid + it * 128, r = i >> 3, c = i & 7;
            uint32_t o = r * 128 + ((c ^ (r & 7)) * 16);
            cp16(sm + QF + o, qsrc + r * 64 + c * 8);
            cp16(sm + KB0 + o, ksrc + r * 64 + c * 8);
        }
        cp_commit();
    }

    uint32_t sw = lane & 7;
    uint32_t cA = lane >> 4;            // 0/1
    uint32_t cB = (lane >> 3) & 1;      // 0/1
    int rA = warp * 16 + (lane & 15);
    uint32_t aQ = sm + QF + rA * 128;
    uint32_t rowBoff[4];
    #pragma unroll
    for (int g = 0; g < 4; g++)
        rowBoff[g] = (uint32_t)((g * 16 + ((lane >> 4) & 1) * 8 + (lane & 7)) * 128);

    int r0 = warp * 16 + gid, r1 = r0 + 8;
    const int* mrow0 = mask + ((size_t)(b * L_ + m0 + r0)) * L_ + tig * 2;
    const int* mrow1 = mask + ((size_t)(b * L_ + m0 + r1)) * L_ + tig * 2;

    // u staging addresses (swizzled within the 8KB tile)
    char* usr0 = smem + US + r0 * 128 + tig * 4;
    char* usr1 = smem + US + r1 * 128 + tig * 4;
    int swr0 = r0 & 7, swr1 = r1 & 7;
    uint4* gUrow = (uint4*)(g_u + (((size_t)b * 32 + (m0 >> 6)) * 32) * 4096);

    float rsa0 = 0.f, rsa1 = 0.f, rsu0 = 0.f, rsu1 = 0.f;

    for (int t = 0; t < 16; t++) {
        int kt = kt0 + t;
        int d = t & 1, n0 = kt * 64;
        cp_wait0();
        __syncthreads();

        // mask prefetch into registers, evict-first (read-once data)
        int2 mk0[8], mk1[8];
        #pragma unroll
        for (int j = 0; j < 8; j++) {
            mk0[j] = __ldcs((const int2*)(mrow0 + n0 + j*8));
            mk1[j] = __ldcs((const int2*)(mrow1 + n0 + j*8));
        }

        if (t < 15) {               // prefetch K(kt+1)
            int d2 = (t + 1) & 1, n2 = (kt + 1) * 64;
            const __half* ksrc = g_Kf + ((size_t)b * L_ + n2) * D_;
            #pragma unroll
            for (int it = 0; it < 4; it++) {
                int i = tid + it * 128, r = i >> 3, c = i & 7;
                uint32_t o = r * 128 + ((c ^ (r & 7)) * 16);
                cp16(sm + KB0 + d2 * 8192 + o, ksrc + r * 64 + c * 8);
            }
            cp_commit();
        }

        // ---- scores: S(16x64) = Q_warp(16x64) · K^T(64x64), single fp16 GEMM
        float accS[8][4];
        #pragma unroll
        for (int j = 0; j < 8; j++)
            #pragma unroll
            for (int x = 0; x < 4; x++) accS[j][x] = 0.f;

        uint32_t kb_base = sm + KB0 + d * 8192;
        #pragma unroll
        for (int kk = 0; kk < 4; kk++) {
            uint32_t oA = ((cA + 2*kk) ^ sw) * 16;
            uint32_t oB = ((cB + 2*kk) ^ sw) * 16;
            uint32_t a[4];
            ldsm_x4(a[0], a[1], a[2], a[3], aQ + oA);
            #pragma unroll
            for (int g = 0; g < 4; g++) {
                uint32_t bfr[4];
                ldsm_x4(bfr[0], bfr[1], bfr[2], bfr[3], kb_base + rowBoff[g] + oB);
                mma_f16(accS[g*2],   a[0], a[1], a[2], a[3], bfr[0], bfr[1]);
                mma_f16(accS[g*2+1], a[0], a[1], a[2], a[3], bfr[2], bfr[3]);
            }
        }

        // ---- epilogue: exp, mask, sums, STS u into swizzled staging tile
        #pragma unroll
        for (int j = 0; j < 8; j++) {
            float e0 = exp2f(accS[j][0] * CE);
            float e1 = exp2f(accS[j][1] * CE);
            float e2 = exp2f(accS[j][2] * CE);
            float e3 = exp2f(accS[j][3] * CE);
            rsa0 += e0 + e1;
            rsa1 += e2 + e3;
            float a0 = mk0[j].x ? 0.f : e0;
            float a1 = mk0[j].y ? 0.f : e1;
            float a2 = mk1[j].x ? 0.f : e2;
            float a3 = mk1[j].y ? 0.f : e3;
            rsu0 += a0 + a1;
            rsu1 += a2 + a3;
            *(__half2*)(usr0 + ((j ^ swr0) * 16)) = __floats2half2_rn(a0, a1);
            *(__half2*)(usr1 + ((j ^ swr1) * 16)) = __floats2half2_rn(a2, a3);
        }
        __syncthreads();   // staging tile complete

        // ---- coalesced streaming STG.128 of the 8KB swizzled tile
        {
            uint4* gU = gUrow + (size_t)kt * 512;
            const uint4* sU = (const uint4*)(smem + US);
            #pragma unroll
            for (int it = 0; it < 4; it++)
                __stcs(gU + tid + it * 128, sU[tid + it * 128]);
        }
    }

    // ---- partial sums: butterfly over tig lanes, write per-z
    #pragma unroll
    for (int o = 1; o <= 2; o <<= 1) {
        rsa0 += __shfl_xor_sync(0xffffffffu, rsa0, o);
        rsa1 += __shfl_xor_sync(0xffffffffu, rsa1, o);
        rsu0 += __shfl_xor_sync(0xffffffffu, rsu0, o);
        rsu1 += __shfl_xor_sync(0xffffffffu, rsu1, o);
    }
    if (tig == 0) {
        g_Psum[z * (B_*L_) + b * L_ + m0 + r0] = make_float2(rsa0, rsu0);
        g_Psum[z * (B_*L_) + b * L_ + m0 + r1] = make_float2(rsa1, rsu1);
    }
}

// ---------------- K2: read tile-blocked u -> attn=u*I write + O += u@V*I (split-K z=2)
// I computed per-thread from g_Psum partials (no smem broadcast -> 7 CTAs/SM).
// grid (L/64, B, 2), block 128. Dyn smem 32768B. atomicAdd into zeroed out.
// layout: U[d] 0+d*8192, V[d] 16384+d*8192
__global__ __launch_bounds__(128, 7) void av_kernel(float* __restrict__ attn,
                                                    float* __restrict__ out) {
    extern __shared__ char smem[];
    const int UB = 0, VB = 16384;
    int b = blockIdx.y, m0 = blockIdx.x * 64, z = blockIdx.z, tid = threadIdx.x;
    int warp = tid >> 5, lane = tid & 31, gid = lane >> 2, tig = lane & 3;
    uint32_t sm = smem_u32(smem);
    int kt0 = z * 16;

    int r0 = warp * 16 + gid, r1 = r0 + 8;

    // fused combine (per-thread): I = 1/(su + 1e-8*sa) from the two split-K partials
    float I0, I1;
    {
        int row0 = b * L_ + m0 + r0, row1 = b * L_ + m0 + r1;
        float2 a0 = g_Psum[row0], b0v = g_Psum[B_*L_ + row0];
        float2 a1 = g_Psum[row1], b1v = g_Psum[B_*L_ + row1];
        I0 = 1.f / ((a0.y + b0v.y) + 1e-8f * (a0.x + b0v.x));
        I1 = 1.f / ((a1.y + b1v.y) + 1e-8f * (a1.x + b1v.x));
    }

    const uint4* gUrow = (const uint4*)(g_u + (((size_t)b * 32 + (m0 >> 6)) * 32) * 4096);

    // prologue: U(kt0) linear copy, V(kt0)
    {
        const uint4* ub = gUrow + (size_t)kt0 * 512;
        #pragma unroll
        for (int it = 0; it < 4; it++)
            cp16(sm + UB + (tid + it * 128) * 16, ub + tid + it * 128);
        #pragma unroll
        for (int it = 0; it < 4; it++) {
            int i = tid + it * 128, r = i >> 3, c = i & 7;
            uint32_t o = r * 128 + ((c ^ (r & 7)) * 16);
            cp16(sm + VB + o, g_VT + ((size_t)b * D_ + r) * L_ + kt0 * 64 + c * 8);
        }
        cp_commit();
    }

    uint32_t sw = lane & 7;
    uint32_t cA = lane >> 4;
    uint32_t cB = (lane >> 3) & 1;
    int rA = warp * 16 + (lane & 15);
    uint32_t rowBoff[4];
    #pragma unroll
    for (int g = 0; g < 4; g++)
        rowBoff[g] = (uint32_t)((g * 16 + ((lane >> 4) & 1) * 8 + (lane & 7)) * 128);

    float accO[8][4];
    #pragma unroll
    for (int j = 0; j < 8; j++)
        #pragma unroll
        for (int x = 0; x < 4; x++) accO[j][x] = 0.f;

    for (int t = 0; t < 16; t++) {
        int kt = kt0 + t;
        int d = t & 1, n0 = kt * 64;
        cp_wait0();
        __syncthreads();

        if (t < 15) {               // prefetch U,V(kt+1)
            int d2 = (t + 1) & 1, n2 = (kt + 1) * 64;
            const uint4* ub = gUrow + (size_t)(kt + 1) * 512;
            #pragma unroll
            for (int it = 0; it < 4; it++)
                cp16(sm + UB + d2 * 8192 + (tid + it * 128) * 16, ub + tid + it * 128);
            #pragma unroll
            for (int it = 0; it < 4; it++) {
                int i = tid + it * 128, r = i >> 3, c = i & 7;
                uint32_t o = r * 128 + ((c ^ (r & 7)) * 16);
                cp16(sm + VB + d2 * 8192 + o, g_VT + ((size_t)b * D_ + r) * L_ + n2 + c * 8);
            }
            cp_commit();
        }

        uint32_t aU = sm + UB + d * 8192 + rA * 128;
        uint32_t vb_base = sm + VB + d * 8192;

        #pragma unroll
        for (int kk = 0; kk < 4; kk++) {
            uint32_t oA = ((cA + 2*kk) ^ sw) * 16;
            uint32_t oB = ((cB + 2*kk) ^ sw) * 16;
            uint32_t ua[4];
            ldsm_x4(ua[0], ua[1], ua[2], ua[3], aU + oA);

            // attn write: fragments -> float2 * I (write-through, never re-read)
            {
                int c = kk * 16 + tig * 2;
                float2 f0 = __half22float2(*(__half2*)&ua[0]);   // (r0, c)
                float2 f1 = __half22float2(*(__half2*)&ua[1]);   // (r1, c)
                float2 f2 = __half22float2(*(__half2*)&ua[2]);   // (r0, c+8)
                float2 f3 = __half22float2(*(__half2*)&ua[3]);   // (r1, c+8)
                size_t ro0 = ((size_t)b * L_ + m0 + r0) * L_ + n0;
                size_t ro1 = ((size_t)b * L_ + m0 + r1) * L_ + n0;
                __stwt((float2*)(attn + ro0 + c),     make_float2(f0.x * I0, f0.y * I0));
                __stwt((float2*)(attn + ro1 + c),     make_float2(f1.x * I1, f1.y * I1));
                __stwt((float2*)(attn + ro0 + c + 8), make_float2(f2.x * I0, f2.y * I0));
                __stwt((float2*)(attn + ro1 + c + 8), make_float2(f3.x * I1, f3.y * I1));
            }

            #pragma unroll
            for (int g = 0; g < 4; g++) {
                uint32_t vf[4];
                ldsm_x4(vf[0], vf[1], vf[2], vf[3], vb_base + rowBoff[g] + oB);
                mma_f16(accO[g*2],   ua[0], ua[1], ua[2], ua[3], vf[0], vf[1]);
                mma_f16(accO[g*2+1], ua[0], ua[1], ua[2], ua[3], vf[2], vf[3]);
            }
        }
    }

    // ---- out epilogue: atomicAdd partial O * I (out pre-zeroed)
    #pragma unroll
    for (int j = 0; j < 8; j++) {
        int c = j*8 + tig*2;
        float* o0 = out + ((size_t)b * L_ + m0 + r0) * D_ + c;
        float* o1 = out + ((size_t)b * L_ + m0 + r1) * D_ + c;
        atomicAdd(o0,     accO[j][0] * I0);
        atomicAdd(o0 + 1, accO[j][1] * I0);
        atomicAdd(o1,     accO[j][2] * I1);
        atomicAdd(o1 + 1, accO[j][3] * I1);
    }
}

// ----------------------------------------------------------------- launcher
extern "C" void kernel_launch(void* const* d_in, const int* in_sizes, int n_in,
                              void* d_out, int out_size) {
    const float* q = (const float*)d_in[0];
    const float* k = (const float*)d_in[1];
    const float* v = (const float*)d_in[2];
    const int* mask = (const int*)d_in[3];
    float* out  = (float*)d_out;
    float* attn = out + (size_t)B_ * L_ * D_;

    cudaFuncSetAttribute(scores_kernel, cudaFuncAttributeMaxDynamicSharedMemorySize, 32768);
    cudaFuncSetAttribute(av_kernel,     cudaFuncAttributeMaxDynamicSharedMemorySize, 32768);

    int n = NE;
    prep_qk<<<dim3((n/2 + 255) / 256, 2), 256>>>(q, k, n);
    vtrans_kernel<<<dim3(L_/32, 2, B_), dim3(32, 8)>>>(v);
    cudaMemsetAsync(out, 0, (size_t)NE * sizeof(float));

    scores_kernel<<<dim3(L_/64, B_, 2), 128, 32768>>>(mask);
    av_kernel<<<dim3(L_/64, B_, 2), 128, 32768>>>(attn, out);
}